// round 3
// baseline (speedup 1.0000x reference)
#include <cuda_runtime.h>
#include <math.h>

#define B_ 32
#define T_ 256
#define V_ 10000
#define E_ 256
#define H_ 512
#define N_ 128
#define WD_ 64
#define R_ 4
#define IFACE_ 471
#define G4H 2048          // 4*H
#define KU 768            // H + R*WD
#define BT_ (B_*T_)       // 8192
#define EPSF 1e-6f
#define NBLK 128
#define THR 256

// ---------------- device scratch ----------------
__device__ __align__(128) float g_X[BT_*E_];
__device__ __align__(128) float g_G0[(size_t)BT_*G4H];
__device__ __align__(128) float g_WihT[E_*G4H];     // permuted cols
__device__ __align__(128) float g_Wt[KU*G4H];       // permuted cols: [rv ; h]
__device__ __align__(128) float g_bl[G4H];          // permuted bias
__device__ __align__(128) float g_U[(size_t)BT_*KU];
__device__ __align__(128) float g_hT[2][H_*B_];     // double-buffered [feat][batch]
__device__ __align__(128) float g_rvT[R_*WD_*B_];
__device__ __align__(128) float g_xiT[IFACE_*B_];
__device__ volatile unsigned g_gen;
__device__ unsigned g_cnt;

__device__ __forceinline__ float sigf(float x){ return 1.f/(1.f + expf(-x)); }
__device__ __forceinline__ float splusf(float x){ return fmaxf(x,0.f) + log1pf(expf(-fabsf(x))); }

// ---------------- grid barrier (all NBLK blocks co-resident) ----------------
__device__ __forceinline__ void gridbar(){
    __syncthreads();
    if (threadIdx.x == 0){
        __threadfence();
        unsigned gen = g_gen;
        if (atomicAdd(&g_cnt, 1u) == NBLK - 1u){
            g_cnt = 0u;
            __threadfence();
            g_gen = gen + 1u;
        } else {
            while (g_gen == gen) { }
        }
        __threadfence();
    }
    __syncthreads();
}

// ---------------- prep kernels ----------------
__global__ void embed_kernel(const int* __restrict__ tok, const float* __restrict__ emb){
    int i = blockIdx.x*256 + threadIdx.x;
    if (i >= BT_*E_) return;
    int bt = i / E_, e = i % E_;
    g_X[i] = tanhf(emb[(size_t)tok[bt]*E_ + e]);
}

// column permutation: new col 4*jj+g  <-  original gate col g*H_+jj
__global__ void prep_w(const float* __restrict__ w_ih, const float* __restrict__ w_hh,
                       const float* __restrict__ b_lstm){
    int i = blockIdx.x*256 + threadIdx.x;
    if (i < KU*G4H){
        int k = i >> 11, col = i & 2047;
        int jj = col >> 2, g = col & 3;
        int j = g*H_ + jj;
        g_Wt[i] = (k < R_*WD_) ? w_ih[(size_t)j*(E_+R_*WD_) + E_ + k]
                               : w_hh[(size_t)j*H_ + (k - R_*WD_)];
    }
    if (i < E_*G4H){
        int e = i >> 11, col = i & 2047;
        int jj = col >> 2, g = col & 3;
        int j = g*H_ + jj;
        g_WihT[i] = w_ih[(size_t)j*(E_+R_*WD_) + e];
    }
    if (i < G4H){
        int jj = i >> 2, g = i & 3;
        g_bl[i] = b_lstm[g*H_ + jj];
    }
}

__global__ void zero_state(){
    int i0 = blockIdx.x*blockDim.x + threadIdx.x;
    int stride = gridDim.x*blockDim.x;
    for (int k=i0;k<2*H_*B_;k+=stride) g_hT[0][k] = 0.f;   // both buffers (contiguous)
    for (int k=i0;k<R_*WD_*B_;k+=stride) g_rvT[k]=0.f;
    if (i0 == 0){ g_cnt = 0u; g_gen = 0u; }
}

// ---------------- generic fp32 tiled SGEMM: C = A(MxK)@B(KxN) (+bias) ----------------
__global__ void sgemm128(const float* __restrict__ A, const float* __restrict__ Bm,
                         const float* __restrict__ bias, float* __restrict__ C,
                         int M, int Nn, int K){
    __shared__ float As[8][128];
    __shared__ float Bs[8][128];
    int tid = threadIdx.x;
    int row0 = blockIdx.y*128, col0 = blockIdx.x*128;
    int trow = (tid >> 4) * 8;
    int tcol = (tid & 15) * 8;
    float acc[8][8];
    #pragma unroll
    for (int i=0;i<8;i++)
        #pragma unroll
        for (int j=0;j<8;j++) acc[i][j]=0.f;

    int arow = tid >> 1, ak = (tid & 1)*4;
    int bk = tid >> 5,  bn = (tid & 31)*4;
    const float* Aptr = A + (size_t)(row0 + arow)*K + ak;

    for (int k0=0;k0<K;k0+=8){
        float4 av = *(const float4*)(Aptr + k0);
        As[ak+0][arow]=av.x; As[ak+1][arow]=av.y; As[ak+2][arow]=av.z; As[ak+3][arow]=av.w;
        float4 bv = make_float4(0.f,0.f,0.f,0.f);
        int gn = col0 + bn;
        if (gn < Nn) bv = *(const float4*)(Bm + (size_t)(k0+bk)*Nn + gn);
        *(float4*)(&Bs[bk][bn]) = bv;
        __syncthreads();
        #pragma unroll
        for (int kk=0;kk<8;kk++){
            float ar[8], br[8];
            *(float4*)(ar)   = *(const float4*)(&As[kk][trow]);
            *(float4*)(ar+4) = *(const float4*)(&As[kk][trow+4]);
            *(float4*)(br)   = *(const float4*)(&Bs[kk][tcol]);
            *(float4*)(br+4) = *(const float4*)(&Bs[kk][tcol+4]);
            #pragma unroll
            for (int i=0;i<8;i++)
                #pragma unroll
                for (int j=0;j<8;j++) acc[i][j] += ar[i]*br[j];
        }
        __syncthreads();
    }
    #pragma unroll
    for (int i=0;i<8;i++){
        size_t gm = (size_t)(row0 + trow + i);
        #pragma unroll
        for (int j=0;j<8;j+=4){
            int gn = col0 + tcol + j;
            if (gn < Nn){
                float4 v = make_float4(acc[i][j],acc[i][j+1],acc[i][j+2],acc[i][j+3]);
                if (bias){ v.x+=bias[gn]; v.y+=bias[gn+1]; v.z+=bias[gn+2]; v.w+=bias[gn+3]; }
                *(float4*)(C + gm*Nn + gn) = v;
            }
        }
    }
}

// ---------------- the persistent sequential loop ----------------
#define DNC_SMEM_FLOATS (128*65 + 128*129 + 512 + 3*128 + 472 + 3*512 + 8*128 + 176 + 128)

__global__ __launch_bounds__(THR) void loop_kernel(const float* __restrict__ W_iface,
                                                   const float* __restrict__ b_iface){
    extern __shared__ float sm[];
    // persistent per-batch state (blocks 0..31)
    float* M_s  = sm;                  // 128*65
    float* L_s  = M_s + 128*65;        // 128*129
    float* wr_s = L_s + 128*129;       // 512
    float* u_s  = wr_s + 512;          // 128
    float* p_s  = u_s + 128;           // 128
    float* ww_s = p_s + 128;           // 128
    // temporaries (also scratch for phases A/C)
    float* xi   = ww_s + 128;          // 472
    float* fwdw = xi + 472;            // 512
    float* bwdw = fwdw + 512;          // 512
    float* crs  = bwdw + 512;          // 512
    float* unew = crs + 512;           // 128
    float* srt  = unew + 128;          // 128
    float* cpex = srt + 128;           // 128
    float* a_s  = cpex + 128;          // 128
    float* cw   = a_s + 128;           // 128 (unused slot, kept for layout)
    float* wwn  = cw + 128;            // 128
    float* Mn   = wwn + 128;           // 128
    float* red  = Mn + 128;            // 128
    float* act  = red + 128;           // 176
    int* rank_s = (int*)(act + 176);   // 128
    (void)cw;

    const int tid  = threadIdx.x;
    const int bx   = blockIdx.x;
    const int wid  = tid >> 5;
    const int lane = tid & 31;
    const int q    = wid & 3;
    const int half = wid >> 2;
    const int b    = bx;

    // init persistent state
    if (bx < B_){
        for (int i=tid;i<128*65;i+=THR)  M_s[i]=0.f;
        for (int i=tid;i<128*129;i+=THR) L_s[i]=0.f;
        for (int i=tid;i<512;i+=THR)     wr_s[i]=0.f;
        if (tid < N_){ u_s[tid]=0.f; p_s[tid]=0.f; ww_s[tid]=0.f; }
        __syncthreads();
    }

    float c_reg = 0.f;     // LSTM cell state, owned by half==0 warps
    const int jj = bx*4 + q;           // gate quad index (0..511)

    for (int t=0;t<T_;t++){
        const int rd = t & 1, wrb = rd ^ 1;

        // ================= Phase A: LSTM gemm + elementwise =================
        {
            float4 acc;
            const float* Wp = g_Wt + 4*jj;
            if (half == 0){
                acc = *(const float4*)(g_G0 + ((size_t)lane*T_ + t)*G4H + 4*jj); // includes bias
                #pragma unroll 8
                for (int k=0;k<R_*WD_;k++){
                    float u = g_rvT[k*B_ + lane];
                    float4 w = *(const float4*)(Wp + (size_t)k*G4H);
                    acc.x += u*w.x; acc.y += u*w.y; acc.z += u*w.z; acc.w += u*w.w;
                }
                const float* hrd = g_hT[rd];
                #pragma unroll 8
                for (int k=0;k<128;k++){
                    float u = hrd[k*B_ + lane];
                    float4 w = *(const float4*)(Wp + (size_t)(R_*WD_ + k)*G4H);
                    acc.x += u*w.x; acc.y += u*w.y; acc.z += u*w.z; acc.w += u*w.w;
                }
            } else {
                acc = make_float4(0.f,0.f,0.f,0.f);
                const float* hrd = g_hT[rd];
                #pragma unroll 8
                for (int k=128;k<H_;k++){
                    float u = hrd[k*B_ + lane];
                    float4 w = *(const float4*)(Wp + (size_t)(R_*WD_ + k)*G4H);
                    acc.x += u*w.x; acc.y += u*w.y; acc.z += u*w.z; acc.w += u*w.w;
                }
            }
            float4* scA = (float4*)xi;    // 8*32 float4 scratch (temp region)
            scA[wid*32 + lane] = acc;
            __syncthreads();
            if (half == 0){
                float4 o = scA[(wid+4)*32 + lane];
                acc.x += o.x; acc.y += o.y; acc.z += o.z; acc.w += o.w;
                // gates: x=gi, y=gf, z=gg, w=go
                float c = sigf(acc.y)*c_reg + sigf(acc.x)*tanhf(acc.z);
                float h = sigf(acc.w)*tanhf(c);
                c_reg = c;
                g_hT[wrb][jj*B_ + lane] = h;
                g_U[((size_t)lane*T_ + t)*KU + jj] = h;
            }
        }
        gridbar();

        // ================= Phase C: iface gemm =================
        {
            const int col = bx*4 + q;
            float accc = 0.f;
            if (col < IFACE_){
                accc = (half == 0) ? b_iface[col] : 0.f;
                const float* hsrc = g_hT[wrb];
                const int k0 = half*256;
                #pragma unroll 8
                for (int k=k0;k<k0+256;k++){
                    accc += hsrc[k*B_ + lane] * W_iface[(size_t)k*IFACE_ + col];
                }
                ((float*)xi)[wid*32 + lane] = accc;
            }
            __syncthreads();
            if (half == 0 && col < IFACE_){
                accc += ((float*)xi)[(wid+4)*32 + lane];
                g_xiT[col*B_ + lane] = accc;
            }
        }
        gridbar();

        // ================= Phase D: DNC memory step (blocks 0..31) =================
        if (bx < B_){
            for (int i=tid;i<IFACE_;i+=THR) xi[i] = g_xiT[i*B_ + b];
            __syncthreads();

            // activations
            if (tid < 64){
                act[8+tid]  = sigf(xi[325+tid]);   // er
                act[72+tid] = xi[389+tid];         // wv
            } else if (tid < 68){
                act[tid-64] = 1.f + splusf(xi[256 + (tid-64)]);  // rb
            } else if (tid == 68){
                act[4] = 1.f + splusf(xi[324]);                  // wb
            } else if (tid < 73){
                act[136 + (tid-69)] = sigf(xi[453 + (tid-69)]);  // fg
            } else if (tid == 73){
                act[140] = sigf(xi[457]);                        // ga
            } else if (tid == 74){
                act[141] = sigf(xi[458]);                        // gw
            } else if (tid < 79){                                // pi softmax
                int r = tid - 75;
                float a0=xi[459+r*3], a1=xi[459+r*3+1], a2=xi[459+r*3+2];
                float m = fmaxf(a0, fmaxf(a1,a2));
                float e0=expf(a0-m), e1=expf(a1-m), e2=expf(a2-m);
                float s = e0+e1+e2;
                act[144+r*3]=e0/s; act[145+r*3]=e1/s; act[146+r*3]=e2/s;
            } else if (tid < 83){                                // ||rk[r]||
                int r = tid - 79; float s = 0.f;
                for (int w=0;w<WD_;w++){ float v = xi[r*WD_+w]; s += v*v; }
                act[156+r] = sqrtf(s);
            } else if (tid == 83){                               // ||wk||
                float s = 0.f;
                for (int w=0;w<WD_;w++){ float v = xi[260+w]; s += v*v; }
                act[160] = sqrtf(s);
            }
            __syncthreads();

            // retention / usage
            if (tid < N_){
                float psi = 1.f;
                #pragma unroll
                for (int r=0;r<R_;r++) psi *= (1.f - act[136+r]*wr_s[r*N_+tid]);
                float uo=u_s[tid], wo=ww_s[tid];
                unew[tid] = (uo + wo - uo*wo)*psi;
            }
            __syncthreads();

            // stable ascending argsort (ranks)
            if (tid < N_){
                float ui = unew[tid]; int rk = 0;
                for (int j=0;j<N_;j++){
                    float uj = unew[j];
                    rk += (uj < ui) || (uj == ui && j < tid);
                }
                rank_s[tid] = rk;
                srt[rk] = ui;
            }
            __syncthreads();
            if (tid == 0){
                float run = 1.f;
                for (int i=0;i<N_;i++){ cpex[i] = run; run *= srt[i]; }
            }
            __syncthreads();

            // allocation + write content score (old M)
            float score_w = 0.f;
            if (tid < N_){
                a_s[tid] = (1.f - unew[tid]) * cpex[rank_s[tid]];
                float s2=0.f, dot=0.f;
                for (int w=0;w<WD_;w++){ float m = M_s[tid*65+w]; s2 += m*m; dot += m*xi[260+w]; }
                score_w = act[4] * (dot / (act[160]*sqrtf(s2) + EPSF));
                red[tid] = score_w;
            }
            __syncthreads();
            for (int s=64;s>0;s>>=1){ if (tid<s) red[tid]=fmaxf(red[tid],red[tid+s]); __syncthreads(); }
            float mxw = red[0];
            __syncthreads();
            float ew = 0.f;
            if (tid < N_){ ew = expf(score_w - mxw); red[tid] = ew; }
            __syncthreads();
            for (int s=64;s>0;s>>=1){ if (tid<s) red[tid]+=red[tid+s]; __syncthreads(); }
            float sden = red[0];
            __syncthreads();
            if (tid < N_){
                wwn[tid] = act[141]*(act[140]*a_s[tid] + (1.f-act[140])*(ew/sden));
                red[tid] = wwn[tid];
            }
            __syncthreads();
            for (int s=64;s>0;s>>=1){ if (tid<s) red[tid]+=red[tid+s]; __syncthreads(); }
            float sumww = red[0];
            __syncthreads();

            // memory write
            for (int i=tid;i<N_*WD_;i+=THR){
                int n=i>>6, w=i&63;
                float wwv = wwn[n];
                M_s[n*65+w] = M_s[n*65+w]*(1.f - wwv*act[8+w]) + wwv*act[72+w];
            }
            // temporal link update (old p)
            for (int i=tid;i<N_*N_;i+=THR){
                int n=i>>7, m=i&127;
                float v = (n==m) ? 0.f
                         : (1.f - wwn[n] - wwn[m])*L_s[n*129+m] + wwn[n]*p_s[m];
                L_s[n*129+m] = v;
            }
            __syncthreads();
            if (tid < N_) p_s[tid] = (1.f - sumww)*p_s[tid] + wwn[tid];

            // forward/backward weights (new L, old wr)
            for (int i=tid;i<R_*N_;i+=THR){
                int r=i>>7, n=i&127;
                float f=0.f, bw=0.f;
                const float* wrr = wr_s + r*N_;
                for (int m=0;m<N_;m++){
                    float wv = wrr[m];
                    f  += L_s[n*129+m]*wv;
                    bw += L_s[m*129+n]*wv;
                }
                fwdw[i]=f; bwdw[i]=bw;
            }
            // read content scores (new M)
            if (tid < N_){
                float s2=0.f;
                for (int w=0;w<WD_;w++){ float m=M_s[tid*65+w]; s2 += m*m; }
                Mn[tid] = sqrtf(s2);
            }
            __syncthreads();
            if (tid < N_){
                #pragma unroll
                for (int r=0;r<R_;r++){
                    float dot=0.f;
                    for (int w=0;w<WD_;w++) dot += M_s[tid*65+w]*xi[r*WD_+w];
                    crs[r*N_+tid] = act[r]*(dot/(act[156+r]*Mn[tid] + EPSF));
                }
            }
            __syncthreads();
            if (tid < 128){
                int r = tid>>5, ln = tid&31;
                float v = fmaxf(fmaxf(crs[r*N_+ln],crs[r*N_+ln+32]),
                                fmaxf(crs[r*N_+ln+64],crs[r*N_+ln+96]));
                #pragma unroll
                for (int o=16;o;o>>=1) v = fmaxf(v, __shfl_xor_sync(0xffffffffu, v, o));
                if (ln==0) act[164+r]=v;
            }
            __syncthreads();
            if (tid < 128){
                int r = tid>>5, ln = tid&31;
                float m = act[164+r];
                float e0=expf(crs[r*N_+ln   ]-m);
                float e1=expf(crs[r*N_+ln+32]-m);
                float e2=expf(crs[r*N_+ln+64]-m);
                float e3=expf(crs[r*N_+ln+96]-m);
                crs[r*N_+ln]=e0; crs[r*N_+ln+32]=e1; crs[r*N_+ln+64]=e2; crs[r*N_+ln+96]=e3;
                float s = e0+e1+e2+e3;
                #pragma unroll
                for (int o=16;o;o>>=1) s += __shfl_xor_sync(0xffffffffu, s, o);
                if (ln==0) act[168+r]=s;
            }
            __syncthreads();
            // new read weights
            for (int i=tid;i<R_*N_;i+=THR){
                int r = i>>7;
                float w = act[144+r*3]*bwdw[i] + act[145+r*3]*(crs[i]/act[168+r]) + act[146+r*3]*fwdw[i];
                crs[i] = w;
            }
            __syncthreads();
            // read vectors rv = wr @ M  (256 threads == 256 outputs)
            {
                int r = tid>>6, w = tid&63;
                float s=0.f;
                for (int n=0;n<N_;n++) s += crs[r*N_+n]*M_s[n*65+w];
                g_rvT[tid*B_ + b] = s;
                g_U[((size_t)b*T_ + t)*KU + H_ + tid] = s;
            }
            __syncthreads();
            // persist state
            for (int i=tid;i<R_*N_;i+=THR) wr_s[i] = crs[i];
            if (tid < N_){ u_s[tid]=unew[tid]; ww_s[tid]=wwn[tid]; }
        }
        gridbar();
    }
}

// ---------------- launcher ----------------
extern "C" void kernel_launch(void* const* d_in, const int* in_sizes, int n_in,
                              void* d_out, int out_size){
    const int*   tokens  = (const int*)  d_in[0];
    const float* emb     = (const float*)d_in[1];
    const float* w_ih    = (const float*)d_in[2];
    const float* w_hh    = (const float*)d_in[3];
    const float* b_lstm  = (const float*)d_in[4];
    const float* W_iface = (const float*)d_in[5];
    const float* b_iface = (const float*)d_in[6];
    const float* W_out   = (const float*)d_in[7];
    const float* b_out   = (const float*)d_in[8];
    float* out = (float*)d_out;

    const int loop_smem = DNC_SMEM_FLOATS * (int)sizeof(float);
    cudaFuncSetAttribute(loop_kernel, cudaFuncAttributeMaxDynamicSharedMemorySize, loop_smem);

    void *pX, *pG0, *pWihT, *pU, *pBl;
    cudaGetSymbolAddress(&pX, g_X);
    cudaGetSymbolAddress(&pG0, g_G0);
    cudaGetSymbolAddress(&pWihT, g_WihT);
    cudaGetSymbolAddress(&pU, g_U);
    cudaGetSymbolAddress(&pBl, g_bl);

    embed_kernel<<<(BT_*E_ + 255)/256, 256>>>(tokens, emb);
    prep_w<<<(KU*G4H + 255)/256, 256>>>(w_ih, w_hh, b_lstm);
    zero_state<<<64, 256>>>();

    // G0 = X (8192x256) @ WihT (256x2048) + permuted bias
    sgemm128<<<dim3(G4H/128, BT_/128), 256>>>((const float*)pX, (const float*)pWihT,
                                              (const float*)pBl, (float*)pG0, BT_, G4H, E_);

    loop_kernel<<<NBLK, THR, loop_smem>>>(W_iface, b_iface);

    // out = U (8192x768) @ W_out (768x10000) + b_out
    sgemm128<<<dim3((V_+127)/128, BT_/128), 256>>>((const float*)pU, W_out,
                                                   b_out, out, BT_, V_, KU);
}

// round 4
// speedup vs baseline: 1.1839x; 1.1839x over previous
#include <cuda_runtime.h>
#include <math.h>

#define B_ 32
#define T_ 256
#define V_ 10000
#define E_ 256
#define H_ 512
#define N_ 128
#define WD_ 64
#define R_ 4
#define IFACE_ 471
#define G4H 2048          // 4*H
#define KU 768            // H + R*WD
#define BT_ (B_*T_)       // 8192
#define EPSF 1e-6f
#define NBLK 128
#define THR 256

// ---------------- device scratch ----------------
__device__ __align__(128) float g_X[BT_*E_];
__device__ __align__(128) float g_G0[(size_t)BT_*G4H];
__device__ __align__(128) float g_WihT[E_*G4H];     // permuted cols
__device__ __align__(128) float g_Wt[KU*G4H];       // permuted cols: [rv ; h]
__device__ __align__(128) float g_bl[G4H];          // permuted bias
__device__ __align__(128) float g_U[(size_t)BT_*KU];
__device__ __align__(128) float g_hT[2][H_*B_];     // double-buffered [feat][batch]
__device__ __align__(128) float g_rvT[R_*WD_*B_];
__device__ __align__(128) float g_xiT[IFACE_*B_];
__device__ volatile unsigned g_gen;
__device__ unsigned g_cnt;

__device__ __forceinline__ float sigf(float x){ return 1.f/(1.f + expf(-x)); }
__device__ __forceinline__ float splusf(float x){ return fmaxf(x,0.f) + log1pf(expf(-fabsf(x))); }

// ---------------- grid barrier (all NBLK blocks co-resident) ----------------
__device__ __forceinline__ void gridbar(){
    __syncthreads();
    if (threadIdx.x == 0){
        __threadfence();
        unsigned gen = g_gen;
        if (atomicAdd(&g_cnt, 1u) == NBLK - 1u){
            g_cnt = 0u;
            __threadfence();
            g_gen = gen + 1u;
        } else {
            while (g_gen == gen) { }
        }
        __threadfence();
    }
    __syncthreads();
}

// ---------------- prep kernels ----------------
__global__ void embed_kernel(const int* __restrict__ tok, const float* __restrict__ emb){
    int i = blockIdx.x*256 + threadIdx.x;
    if (i >= BT_*E_) return;
    int bt = i / E_, e = i % E_;
    g_X[i] = tanhf(emb[(size_t)tok[bt]*E_ + e]);
}

// column permutation: new col 4*jj+g  <-  original gate col g*H_+jj
__global__ void prep_w(const float* __restrict__ w_ih, const float* __restrict__ w_hh,
                       const float* __restrict__ b_lstm){
    int i = blockIdx.x*256 + threadIdx.x;
    if (i < KU*G4H){
        int k = i >> 11, col = i & 2047;
        int jj = col >> 2, g = col & 3;
        int j = g*H_ + jj;
        g_Wt[i] = (k < R_*WD_) ? w_ih[(size_t)j*(E_+R_*WD_) + E_ + k]
                               : w_hh[(size_t)j*H_ + (k - R_*WD_)];
    }
    if (i < E_*G4H){
        int e = i >> 11, col = i & 2047;
        int jj = col >> 2, g = col & 3;
        int j = g*H_ + jj;
        g_WihT[i] = w_ih[(size_t)j*(E_+R_*WD_) + e];
    }
    if (i < G4H){
        int jj = i >> 2, g = i & 3;
        g_bl[i] = b_lstm[g*H_ + jj];
    }
}

__global__ void zero_state(){
    int i0 = blockIdx.x*blockDim.x + threadIdx.x;
    int stride = gridDim.x*blockDim.x;
    for (int k=i0;k<2*H_*B_;k+=stride) g_hT[0][k] = 0.f;
    for (int k=i0;k<R_*WD_*B_;k+=stride) g_rvT[k]=0.f;
    if (i0 == 0){ g_cnt = 0u; g_gen = 0u; }
}

// ---------------- pipelined fp32 SGEMM: C = A(MxK)@B(KxN) (+bias) ----------------
__global__ __launch_bounds__(256) void sgemm128(const float* __restrict__ A,
                         const float* __restrict__ Bm,
                         const float* __restrict__ bias, float* __restrict__ C,
                         int M, int Nn, int K){
    __shared__ float As[2][8][128];
    __shared__ float Bs[2][8][128];
    int tid = threadIdx.x;
    int row0 = blockIdx.y*128, col0 = blockIdx.x*128;
    int trow = (tid >> 4) * 8;
    int tcol = (tid & 15) * 8;
    float acc[8][8];
    #pragma unroll
    for (int i=0;i<8;i++)
        #pragma unroll
        for (int j=0;j<8;j++) acc[i][j]=0.f;

    int arow = tid >> 1, ak = (tid & 1)*4;
    int bk = tid >> 5,  bn = (tid & 31)*4;
    const float* Aptr = A + (size_t)(row0 + arow)*K + ak;
    int gn = col0 + bn;

    float4 av = *(const float4*)(Aptr);
    float4 bv = make_float4(0.f,0.f,0.f,0.f);
    if (gn < Nn) bv = *(const float4*)(Bm + (size_t)bk*Nn + gn);
    As[0][ak+0][arow]=av.x; As[0][ak+1][arow]=av.y; As[0][ak+2][arow]=av.z; As[0][ak+3][arow]=av.w;
    *(float4*)(&Bs[0][bk][bn]) = bv;
    __syncthreads();

    int buf = 0;
    for (int k0=0;k0<K;k0+=8){
        bool more = (k0 + 8) < K;
        if (more){
            av = *(const float4*)(Aptr + k0 + 8);
            bv = make_float4(0.f,0.f,0.f,0.f);
            if (gn < Nn) bv = *(const float4*)(Bm + (size_t)(k0+8+bk)*Nn + gn);
        }
        #pragma unroll
        for (int kk=0;kk<8;kk++){
            float ar[8], br[8];
            *(float4*)(ar)   = *(const float4*)(&As[buf][kk][trow]);
            *(float4*)(ar+4) = *(const float4*)(&As[buf][kk][trow+4]);
            *(float4*)(br)   = *(const float4*)(&Bs[buf][kk][tcol]);
            *(float4*)(br+4) = *(const float4*)(&Bs[buf][kk][tcol+4]);
            #pragma unroll
            for (int i=0;i<8;i++)
                #pragma unroll
                for (int j=0;j<8;j++) acc[i][j] += ar[i]*br[j];
        }
        if (more){
            int nb = buf ^ 1;
            As[nb][ak+0][arow]=av.x; As[nb][ak+1][arow]=av.y; As[nb][ak+2][arow]=av.z; As[nb][ak+3][arow]=av.w;
            *(float4*)(&Bs[nb][bk][bn]) = bv;
            __syncthreads();
            buf = nb;
        }
    }
    #pragma unroll
    for (int i=0;i<8;i++){
        size_t gm = (size_t)(row0 + trow + i);
        #pragma unroll
        for (int j=0;j<8;j+=4){
            int gnn = col0 + tcol + j;
            if (gnn < Nn){
                float4 v = make_float4(acc[i][j],acc[i][j+1],acc[i][j+2],acc[i][j+3]);
                if (bias){ v.x+=bias[gnn]; v.y+=bias[gnn+1]; v.z+=bias[gnn+2]; v.w+=bias[gnn+3]; }
                *(float4*)(C + gm*Nn + gnn) = v;
            }
        }
    }
}

// ---------------- persistent sequential loop ----------------
// smem floats: W_A 12288 | W_C 2048 | scr 4096 | DNC 29064  => 47496 floats = 189984 B
#define LOOP_SMEM_FLOATS (12288 + 2048 + 4096 + (128*65 + 128*129 + 512 + 3*128 + 472 + 3*512 + 9*128 + 176 + 128))

__global__ __launch_bounds__(THR) void loop_kernel(const float* __restrict__ W_iface,
                                                   const float* __restrict__ b_iface){
    extern __shared__ float sm[];
    float* W_A  = sm;                  // 768*16
    float* W_C  = W_A + 12288;         // 512*4
    float* scr  = W_C + 2048;          // 4096
    float* M_s  = scr + 4096;          // 128*65
    float* L_s  = M_s + 8320;          // 128*129
    float* wr_s = L_s + 16512;         // 512
    float* u_s  = wr_s + 512;          // 128
    float* p_s  = u_s + 128;           // 128
    float* ww_s = p_s + 128;           // 128
    float* xi   = ww_s + 128;          // 472
    float* fwdw = xi + 472;            // 512
    float* bwdw = fwdw + 512;          // 512
    float* crs  = bwdw + 512;          // 512
    float* unew = crs + 512;           // 128
    float* srt  = unew + 128;          // 128
    float* incl = srt + 128;           // 128
    float* cpex = incl + 128;          // 128
    float* a_s  = cpex + 128;          // 128
    float* wwn  = a_s + 128;           // 128
    float* Mn   = wwn + 128;           // 128
    float* red  = Mn + 128;            // 128
    float* xtra = red + 128;           // 128 (spare)
    float* act  = xtra + 128;          // 176
    int* rank_s = (int*)(act + 176);   // 128
    (void)xtra;

    const int tid  = threadIdx.x;
    const int bx   = blockIdx.x;
    const int wid  = tid >> 5;
    const int lane = tid & 31;
    const int b    = bx;

    // ---- stage time-invariant weights into smem (once) ----
    for (int i=tid;i<768*16;i+=THR){
        int k = i >> 4, c = i & 15;
        W_A[i] = g_Wt[(size_t)k*G4H + bx*16 + c];
    }
    for (int i=tid;i<512*4;i+=THR){
        int k = i >> 2, c = i & 3;
        int col = bx*4 + c;
        W_C[i] = (col < IFACE_) ? W_iface[(size_t)k*IFACE_ + col] : 0.f;
    }
    // ---- init persistent DNC state ----
    if (bx < B_){
        for (int i=tid;i<128*65;i+=THR)  M_s[i]=0.f;
        for (int i=tid;i<128*129;i+=THR) L_s[i]=0.f;
        for (int i=tid;i<512;i+=THR)     wr_s[i]=0.f;
        if (tid < N_){ u_s[tid]=0.f; p_s[tid]=0.f; ww_s[tid]=0.f; }
    }
    __syncthreads();

    float c_reg = 0.f;   // LSTM cell state: threads tid<128 own (unit=tid>>5, batch=lane)

    for (int t=0;t<T_;t++){
        const int rd = t & 1, wrb = rd ^ 1;

        // ================= Phase A: LSTM gemm (split-K over 8 warps) =================
        {
            const int kbeg = wid*96;
            float acc[16];
            #pragma unroll
            for (int c=0;c<16;c++) acc[c]=0.f;
            const float* hrd = g_hT[rd];
            #pragma unroll 4
            for (int k=kbeg;k<kbeg+96;k++){
                const float* ap = (k < 256) ? (g_rvT + k*B_) : (hrd + (k-256)*B_);
                float a = ap[lane];
                const float4* wp = (const float4*)(W_A + k*16);
                float4 w0=wp[0], w1=wp[1], w2=wp[2], w3=wp[3];
                acc[0] += a*w0.x; acc[1] += a*w0.y; acc[2] += a*w0.z; acc[3] += a*w0.w;
                acc[4] += a*w1.x; acc[5] += a*w1.y; acc[6] += a*w1.z; acc[7] += a*w1.w;
                acc[8] += a*w2.x; acc[9] += a*w2.y; acc[10]+= a*w2.z; acc[11]+= a*w2.w;
                acc[12]+= a*w3.x; acc[13]+= a*w3.y; acc[14]+= a*w3.z; acc[15]+= a*w3.w;
            }
            #pragma unroll
            for (int c=0;c<16;c++) scr[wid*512 + c*32 + lane] = acc[c];
        }
        __syncthreads();
        if (tid < 128){
            int uu = tid >> 5;
            float4 s = *(const float4*)(g_G0 + ((size_t)lane*T_ + t)*G4H + bx*16 + uu*4);
            #pragma unroll
            for (int w8=0;w8<8;w8++){
                const float* pp = scr + w8*512 + uu*128 + lane;
                s.x += pp[0]; s.y += pp[32]; s.z += pp[64]; s.w += pp[96];
            }
            float c = sigf(s.y)*c_reg + sigf(s.x)*tanhf(s.z);
            float h = sigf(s.w)*tanhf(c);
            c_reg = c;
            int jj = bx*4 + uu;
            g_hT[wrb][jj*B_ + lane] = h;
            g_U[((size_t)lane*T_ + t)*KU + jj] = h;
        }
        gridbar();

        // ================= Phase C: iface gemm (split-K over 8 warps) =================
        if (bx < 118){
            const int kbeg = wid*64;
            float a0=0.f,a1=0.f,a2=0.f,a3=0.f;
            const float* hsrc = g_hT[wrb];
            #pragma unroll 4
            for (int k=kbeg;k<kbeg+64;k++){
                float a = hsrc[k*B_ + lane];
                float4 wv = *(const float4*)(W_C + k*4);
                a0 += a*wv.x; a1 += a*wv.y; a2 += a*wv.z; a3 += a*wv.w;
            }
            scr[wid*128 +       lane] = a0;
            scr[wid*128 +  32 + lane] = a1;
            scr[wid*128 +  64 + lane] = a2;
            scr[wid*128 +  96 + lane] = a3;
            __syncthreads();
            if (tid < 128){
                int c = tid >> 5, col = bx*4 + c;
                if (col < IFACE_){
                    float s = b_iface[col];
                    #pragma unroll
                    for (int w8=0;w8<8;w8++) s += scr[w8*128 + c*32 + lane];
                    g_xiT[col*B_ + lane] = s;
                }
            }
        }
        gridbar();

        // ================= Phase D: DNC memory step (blocks 0..31) =================
        if (bx < B_){
            for (int i=tid;i<IFACE_;i+=THR) xi[i] = g_xiT[i*B_ + b];
            __syncthreads();

            // activations
            if (tid < 64){
                act[8+tid]  = sigf(xi[325+tid]);   // er
                act[72+tid] = xi[389+tid];         // wv
            } else if (tid < 68){
                act[tid-64] = 1.f + splusf(xi[256 + (tid-64)]);  // rb
            } else if (tid == 68){
                act[4] = 1.f + splusf(xi[324]);                  // wb
            } else if (tid < 73){
                act[136 + (tid-69)] = sigf(xi[453 + (tid-69)]);  // fg
            } else if (tid == 73){
                act[140] = sigf(xi[457]);                        // ga
            } else if (tid == 74){
                act[141] = sigf(xi[458]);                        // gw
            } else if (tid < 79){                                // pi softmax
                int r = tid - 75;
                float q0=xi[459+r*3], q1=xi[459+r*3+1], q2=xi[459+r*3+2];
                float m = fmaxf(q0, fmaxf(q1,q2));
                float e0=expf(q0-m), e1=expf(q1-m), e2=expf(q2-m);
                float s = e0+e1+e2;
                act[144+r*3]=e0/s; act[145+r*3]=e1/s; act[146+r*3]=e2/s;
            } else if (tid < 83){                                // ||rk[r]||
                int r = tid - 79; float s = 0.f;
                for (int w=0;w<WD_;w++){ float v = xi[r*WD_+w]; s += v*v; }
                act[156+r] = sqrtf(s);
            } else if (tid == 83){                               // ||wk||
                float s = 0.f;
                for (int w=0;w<WD_;w++){ float v = xi[260+w]; s += v*v; }
                act[160] = sqrtf(s);
            }
            __syncthreads();

            // retention / usage
            if (tid < N_){
                float psi = 1.f;
                #pragma unroll
                for (int r=0;r<R_;r++) psi *= (1.f - act[136+r]*wr_s[r*N_+tid]);
                float uo=u_s[tid], wo=ww_s[tid];
                unew[tid] = (uo + wo - uo*wo)*psi;
            }
            __syncthreads();

            // stable ascending argsort via ranks
            if (tid < N_){
                float ui = unew[tid]; int rk = 0;
                for (int j=0;j<N_;j++){
                    float uj = unew[j];
                    rk += (uj < ui) || (uj == ui && j < tid);
                }
                rank_s[tid] = rk;
                srt[rk] = ui;
            }
            __syncthreads();

            // parallel cumprod of srt (exclusive) -> cpex
            float cp_p = 1.f;
            if (tid < N_){
                int w4 = tid >> 5, ln = tid & 31;
                cp_p = srt[tid];
                #pragma unroll
                for (int off=1;off<32;off<<=1){
                    float o = __shfl_up_sync(0xffffffffu, cp_p, off);
                    if (ln >= off) cp_p *= o;
                }
                if (ln == 31) red[w4] = cp_p;
            }
            __syncthreads();
            if (tid < N_){
                int w4 = tid >> 5;
                float pre = 1.f;
                #pragma unroll
                for (int j=0;j<3;j++) if (j < w4) pre *= red[j];
                incl[tid] = cp_p * pre;
            }
            __syncthreads();
            if (tid < N_) cpex[tid] = (tid == 0) ? 1.f : incl[tid-1];
            __syncthreads();

            // allocation + write content score (old M)
            float score_w = 0.f, ew = 0.f;
            if (tid < N_){
                a_s[tid] = (1.f - unew[tid]) * cpex[rank_s[tid]];
                float s2=0.f, dot=0.f;
                for (int w=0;w<WD_;w++){ float m = M_s[tid*65+w]; s2 += m*m; dot += m*xi[260+w]; }
                score_w = act[4] * (dot / (act[160]*sqrtf(s2) + EPSF));
                float v = score_w;
                #pragma unroll
                for (int o=16;o;o>>=1) v = fmaxf(v, __shfl_xor_sync(0xffffffffu, v, o));
                if ((tid&31)==0) red[tid>>5] = v;
            }
            __syncthreads();
            float mxw = fmaxf(fmaxf(red[0],red[1]), fmaxf(red[2],red[3]));
            if (tid < N_){
                ew = expf(score_w - mxw);
                float s = ew;
                #pragma unroll
                for (int o=16;o;o>>=1) s += __shfl_xor_sync(0xffffffffu, s, o);
                if ((tid&31)==0) red[4 + (tid>>5)] = s;
            }
            __syncthreads();
            float sden = red[4]+red[5]+red[6]+red[7];
            if (tid < N_){
                float wv = act[141]*(act[140]*a_s[tid] + (1.f-act[140])*(ew/sden));
                wwn[tid] = wv;
                float s = wv;
                #pragma unroll
                for (int o=16;o;o>>=1) s += __shfl_xor_sync(0xffffffffu, s, o);
                if ((tid&31)==0) red[8 + (tid>>5)] = s;
            }
            __syncthreads();
            float sumww = red[8]+red[9]+red[10]+red[11];

            // memory write (new M)
            for (int i=tid;i<N_*WD_;i+=THR){
                int n=i>>6, w=i&63;
                float wwv = wwn[n];
                M_s[n*65+w] = M_s[n*65+w]*(1.f - wwv*act[8+w]) + wwv*act[72+w];
            }
            // temporal link update (old p)
            for (int i=tid;i<N_*N_;i+=THR){
                int n=i>>7, m=i&127;
                float v = (n==m) ? 0.f
                         : (1.f - wwn[n] - wwn[m])*L_s[n*129+m] + wwn[n]*p_s[m];
                L_s[n*129+m] = v;
            }
            __syncthreads();
            if (tid < N_) p_s[tid] = (1.f - sumww)*p_s[tid] + wwn[tid];

            // forward/backward weights (new L, old wr)
            for (int i=tid;i<R_*N_;i+=THR){
                int r=i>>7, n=i&127;
                float f=0.f, bw=0.f;
                const float* wrr = wr_s + r*N_;
                for (int m=0;m<N_;m++){
                    float wv = wrr[m];
                    f  += L_s[n*129+m]*wv;
                    bw += L_s[m*129+n]*wv;
                }
                fwdw[i]=f; bwdw[i]=bw;
            }
            // read content scores (new M)
            if (tid < N_){
                float s2=0.f;
                for (int w=0;w<WD_;w++){ float m=M_s[tid*65+w]; s2 += m*m; }
                Mn[tid] = sqrtf(s2);
            }
            __syncthreads();
            if (tid < N_){
                #pragma unroll
                for (int r=0;r<R_;r++){
                    float dot=0.f;
                    for (int w=0;w<WD_;w++) dot += M_s[tid*65+w]*xi[r*WD_+w];
                    crs[r*N_+tid] = act[r]*(dot/(act[156+r]*Mn[tid] + EPSF));
                }
            }
            __syncthreads();
            if (tid < 128){
                int r = tid>>5, ln = tid&31;
                float v = fmaxf(fmaxf(crs[r*N_+ln],crs[r*N_+ln+32]),
                                fmaxf(crs[r*N_+ln+64],crs[r*N_+ln+96]));
                #pragma unroll
                for (int o=16;o;o>>=1) v = fmaxf(v, __shfl_xor_sync(0xffffffffu, v, o));
                if (ln==0) act[164+r]=v;
            }
            __syncthreads();
            if (tid < 128){
                int r = tid>>5, ln = tid&31;
                float m = act[164+r];
                float e0=expf(crs[r*N_+ln   ]-m);
                float e1=expf(crs[r*N_+ln+32]-m);
                float e2=expf(crs[r*N_+ln+64]-m);
                float e3=expf(crs[r*N_+ln+96]-m);
                crs[r*N_+ln]=e0; crs[r*N_+ln+32]=e1; crs[r*N_+ln+64]=e2; crs[r*N_+ln+96]=e3;
                float s = e0+e1+e2+e3;
                #pragma unroll
                for (int o=16;o;o>>=1) s += __shfl_xor_sync(0xffffffffu, s, o);
                if (ln==0) act[168+r]=s;
            }
            __syncthreads();
            // new read weights
            for (int i=tid;i<R_*N_;i+=THR){
                int r = i>>7;
                float w = act[144+r*3]*bwdw[i] + act[145+r*3]*(crs[i]/act[168+r]) + act[146+r*3]*fwdw[i];
                crs[i] = w;
            }
            __syncthreads();
            // read vectors rv = wr @ M
            {
                int r = tid>>6, w = tid&63;
                float s=0.f;
                for (int n=0;n<N_;n++) s += crs[r*N_+n]*M_s[n*65+w];
                g_rvT[tid*B_ + b] = s;
                g_U[((size_t)b*T_ + t)*KU + H_ + tid] = s;
            }
            __syncthreads();
            // persist state
            for (int i=tid;i<R_*N_;i+=THR) wr_s[i] = crs[i];
            if (tid < N_){ u_s[tid]=unew[tid]; ww_s[tid]=wwn[tid]; }
        }
        gridbar();
    }
}

// ---------------- launcher ----------------
extern "C" void kernel_launch(void* const* d_in, const int* in_sizes, int n_in,
                              void* d_out, int out_size){
    const int*   tokens  = (const int*)  d_in[0];
    const float* emb     = (const float*)d_in[1];
    const float* w_ih    = (const float*)d_in[2];
    const float* w_hh    = (const float*)d_in[3];
    const float* b_lstm  = (const float*)d_in[4];
    const float* W_iface = (const float*)d_in[5];
    const float* b_iface = (const float*)d_in[6];
    const float* W_out   = (const float*)d_in[7];
    const float* b_out   = (const float*)d_in[8];
    float* out = (float*)d_out;

    const int loop_smem = LOOP_SMEM_FLOATS * (int)sizeof(float);
    cudaFuncSetAttribute(loop_kernel, cudaFuncAttributeMaxDynamicSharedMemorySize, loop_smem);

    void *pX, *pG0, *pWihT, *pU, *pBl;
    cudaGetSymbolAddress(&pX, g_X);
    cudaGetSymbolAddress(&pG0, g_G0);
    cudaGetSymbolAddress(&pWihT, g_WihT);
    cudaGetSymbolAddress(&pU, g_U);
    cudaGetSymbolAddress(&pBl, g_bl);

    embed_kernel<<<(BT_*E_ + 255)/256, 256>>>(tokens, emb);
    prep_w<<<(KU*G4H + 255)/256, 256>>>(w_ih, w_hh, b_lstm);
    zero_state<<<64, 256>>>();

    // G0 = X (8192x256) @ WihT (256x2048) + permuted bias
    sgemm128<<<dim3(G4H/128, BT_/128), 256>>>((const float*)pX, (const float*)pWihT,
                                              (const float*)pBl, (float*)pG0, BT_, G4H, E_);

    loop_kernel<<<NBLK, THR, loop_smem>>>(W_iface, b_iface);

    // out = U (8192x768) @ W_out (768x10000) + b_out
    sgemm128<<<dim3((V_+127)/128, BT_/128), 256>>>((const float*)pU, W_out,
                                                   b_out, out, BT_, V_, KU);
}